// round 8
// baseline (speedup 1.0000x reference)
#include <cuda_runtime.h>
#include <cstdint>

// Shapes (fixed by the problem instance)
#define B_  4
#define H_  96
#define W_  96
#define D_  96
#define NWH 12            // 96/8
#define NUM_WIN 1728      // 12*12*12
#define LEN_KEEP 691      // int(1728*0.4)
#define KSEL (LEN_KEEP-1) // 0-indexed rank of the threshold key
#define LEN_MASK (NUM_WIN - LEN_KEEP)    // 1037
#define ELEMS_PER_OUT (B_*H_*W_*D_*32)   // 113,246,208 floats

// phase blocks: each handles ONE output stream of ONE window (64 KB)
#define COPY_BLOCKS (B_ * LEN_KEEP)   // 2764: kept  -> xm copy (1R:1W)
#define ONES_BLOCKS (B_ * LEN_MASK)   // 4148: masked-> mk = 1 (pure write)
#define PHASE_BLOCKS (2*COPY_BLOCKS + 2*ONES_BLOCKS)   // 13824
#define GRID_BLOCKS (B_ + PHASE_BLOCKS)                // 13828

// window-ordered compact lists of global window ids (b*1728+i)
__device__ int g_kept_list[B_ * LEN_KEEP];
__device__ int g_masked_list[B_ * LEN_MASK];
__device__ int g_flag;   // # batches whose lists are ready (0..4)
__device__ int g_fin;    // finished-block counter (replay-safe reset)

__device__ __forceinline__ int warp_incl_scan(int v, int lane) {
#pragma unroll
    for (int o = 1; o < 32; o <<= 1) {
        int u = __shfl_up_sync(0xFFFFFFFFu, v, o);
        if (lane >= o) v += u;
    }
    return v;
}

// inclusive scan of v across 512 threads (16 warps); wsum = shared int[16]
__device__ __forceinline__ int block_incl_scan512(int v, int lane, int wid,
                                                  int* wsum) {
    __syncthreads();                 // protect wsum reuse
    v = warp_incl_scan(v, lane);
    if (lane == 31) wsum[wid] = v;
    __syncthreads();
    if (wid == 0) {
        int w = (lane < 16) ? wsum[lane] : 0;
        w = warp_incl_scan(w, lane);
        if (lane < 16) wsum[lane] = w;
    }
    __syncthreads();
    return v + (wid > 0 ? wsum[wid - 1] : 0);
}

struct PrepSmem {
    unsigned int sbits[NUM_WIN];
    int hist[2048];
    int wsum[16];
    int s_bucket, s_below;
    unsigned long long cand[128];
    int cand_cnt;
    unsigned long long s_thresh;
};

// ---------------------------------------------------------------------------
// Fused kernel. bid 0..3: prep (O(n) selection + window-ordered compaction,
// one block per batch), release g_flag. bid >= 4: phase blocks — spin until
// g_flag==4, then each writes ONE output stream of ONE window:
//   [copy kept->xm][ones masked->mk][zeros masked->xm][zeros kept->mk]
// Last exiting block resets g_flag/g_fin -> deterministic across graph
// replays.
// ---------------------------------------------------------------------------
__global__ void __launch_bounds__(512)
fused_kernel(const float4* __restrict__ x,
             float4* __restrict__ out_xm,
             float4* __restrict__ out_mk,
             const float* __restrict__ noise) {
    __shared__ PrepSmem ps;
    const int bid  = blockIdx.x;
    const int tid  = threadIdx.x;
    const int lane = tid & 31;
    const int wid  = tid >> 5;

    if (bid < B_) {
        // ================= prep: one block per batch =================
        const int b = bid;
        for (int t = tid; t < NUM_WIN; t += 512)
            ps.sbits[t] = __float_as_uint(noise[b * NUM_WIN + t]);
        for (int t = tid; t < 2048; t += 512)
            ps.hist[t] = 0;
        if (tid == 0) ps.cand_cnt = 0;
        __syncthreads();

        for (int t = tid; t < NUM_WIN; t += 512) {
            float v = __uint_as_float(ps.sbits[t]);
            int bk = (int)(v * 2048.0f);
            bk = bk < 0 ? 0 : (bk > 2047 ? 2047 : bk);
            atomicAdd(&ps.hist[bk], 1);
        }
        __syncthreads();

        // scan of 2048 bucket counts, 4 per thread -> find bucket w/ rank 690
        int a[4], ts = 0;
#pragma unroll
        for (int k = 0; k < 4; k++) { a[k] = ps.hist[4 * tid + k]; ts += a[k]; }
        const int incl = block_incl_scan512(ts, lane, wid, ps.wsum);
        int e = incl - ts;
#pragma unroll
        for (int k = 0; k < 4; k++) {
            if (KSEL >= e && KSEL < e + a[k]) { ps.s_bucket = 4 * tid + k; ps.s_below = e; }
            e += a[k];
        }
        __syncthreads();

        // gather candidates in the target bucket, rank exactly -> threshold
        const int tb = ps.s_bucket;
        for (int t = tid; t < NUM_WIN; t += 512) {
            float fv = __uint_as_float(ps.sbits[t]);
            int bk = (int)(fv * 2048.0f);
            bk = bk < 0 ? 0 : (bk > 2047 ? 2047 : bk);
            if (bk == tb) {
                int p = atomicAdd(&ps.cand_cnt, 1);
                if (p < 128)
                    ps.cand[p] = ((unsigned long long)ps.sbits[t] << 11) | (unsigned)t;
            }
        }
        __syncthreads();
        const int m = ps.cand_cnt < 128 ? ps.cand_cnt : 128;
        const int need = KSEL - ps.s_below;
        if (tid < m) {
            unsigned long long k = ps.cand[tid];
            int c = 0;
            for (int j = 0; j < m; j++) c += (ps.cand[j] < k);
            if (c == need) ps.s_thresh = k;
        }
        __syncthreads();
        const unsigned long long thresh = ps.s_thresh;

        // window-ordered compaction: threads 0..431 x 4 consecutive windows
        int kept[4] = {0, 0, 0, 0};
        int cnt = 0;
        if (tid < 432) {
#pragma unroll
            for (int k = 0; k < 4; k++) {
                const int j = 4 * tid + k;
                unsigned long long key =
                    ((unsigned long long)ps.sbits[j] << 11) | (unsigned)j;
                kept[k] = (key <= thresh);
                cnt += kept[k];
            }
        }
        const int incl2 = block_incl_scan512(cnt, lane, wid, ps.wsum);
        if (tid < 432) {
            int kp = incl2 - cnt;     // kept windows before window 4*tid
            const int gw = b * NUM_WIN;
#pragma unroll
            for (int k = 0; k < 4; k++) {
                const int j = 4 * tid + k;
                if (kept[k]) { g_kept_list[b * LEN_KEEP + kp] = gw + j; kp++; }
                else           g_masked_list[b * LEN_MASK + (j - kp)] = gw + j;
            }
        }
        __threadfence();
        __syncthreads();
        if (tid == 0) atomicAdd(&g_flag, 1);   // release this batch
    } else {
        // ================= phase block =================
        const int pbid = bid - B_;
        int phase, lk;
        if (pbid < COPY_BLOCKS)                        { phase = 0; lk = pbid; }
        else if (pbid < COPY_BLOCKS + ONES_BLOCKS)     { phase = 1; lk = pbid - COPY_BLOCKS; }
        else if (pbid < COPY_BLOCKS + 2 * ONES_BLOCKS) { phase = 2; lk = pbid - COPY_BLOCKS - ONES_BLOCKS; }
        else                                           { phase = 3; lk = pbid - COPY_BLOCKS - 2 * ONES_BLOCKS; }
        const bool from_masked = (phase == 1) || (phase == 2);

        const int seg   = tid >> 3;        // 0..63 window segment
        const int lane8 = tid & 7;
        const int dh = seg >> 3;
        const int dw = seg & 7;

        // wait for prep (wave-1 blocks spin ~2-3us; later waves pass through)
        if (tid == 0) {
            while (*(volatile int*)&g_flag < B_) __nanosleep(64);
        }
        __syncthreads();
        __threadfence();                   // acquire before list reads

        const int wglob = from_masked ? __ldg(&g_masked_list[lk])
                                      : __ldg(&g_kept_list[lk]);

        const int b   = wglob / NUM_WIN;
        const int i   = wglob - b * NUM_WIN;
        const int wd3 = i % NWH;
        const int r   = i / NWH;
        const int ww3 = r % NWH;
        const int wh3 = r / NWH;

        const int h = wh3 * 8 + dh;
        const int w = ww3 * 8 + dw;
        // float4 base of this segment (8 voxels along d, 32 ch = 64 float4)
        const int s0 = (((b * H_ + h) * W_ + w) * D_ + wd3 * 8) * 8 + lane8;

        if (phase == 0) {
            float4 v[8];
#pragma unroll
            for (int k = 0; k < 8; k++)
                v[k] = __ldcs(&x[s0 + k * 8]);
#pragma unroll
            for (int k = 0; k < 8; k++)
                __stcs(&out_xm[s0 + k * 8], v[k]);
        } else {
            const float fv = (phase == 1) ? 1.0f : 0.0f;
            const float4 c = make_float4(fv, fv, fv, fv);
            float4* outp = (phase == 2) ? out_xm : out_mk;
#pragma unroll
            for (int k = 0; k < 8; k++)
                __stcs(&outp[s0 + k * 8], c);
        }
    }

    // ---- replay-safe reset: last exiting block zeroes the sync state ----
    __syncthreads();
    if (tid == 0) {
        const int n = atomicAdd(&g_fin, 1);
        if (n == GRID_BLOCKS - 1) {
            g_flag = 0;
            g_fin  = 0;
        }
    }
}

extern "C" void kernel_launch(void* const* d_in, const int* in_sizes, int n_in,
                              void* d_out, int out_size) {
    const float* x     = (const float*)d_in[0];   // [B,H,W,D,C] fp32
    const float* noise = (const float*)d_in[1];   // [B, 1728]   fp32
    float* out = (float*)d_out;                   // [x_masked | mask]

    fused_kernel<<<GRID_BLOCKS, 512>>>(
        (const float4*)x,
        (float4*)out,
        (float4*)(out + (long long)ELEMS_PER_OUT),
        noise);
}

// round 9
// speedup vs baseline: 1.0387x; 1.0387x over previous
#include <cuda_runtime.h>
#include <cstdint>

// Shapes (fixed by the problem instance)
#define B_  4
#define H_  96
#define W_  96
#define D_  96
#define NWH 12            // 96/8
#define NUM_WIN 1728      // 12*12*12
#define LEN_KEEP 691      // int(1728*0.4)
#define KSEL (LEN_KEEP-1) // 0-indexed rank of the threshold key
#define LEN_MASK (NUM_WIN - LEN_KEEP)    // 1037
#define ELEMS_PER_OUT (B_*H_*W_*D_*32)   // 113,246,208 floats

// block phases: each block handles ONE output stream of ONE window (64 KB)
#define COPY_BLOCKS (B_ * LEN_KEEP)   // 2764: kept -> xm copy (1R:1W)
#define ONES_BLOCKS (B_ * LEN_MASK)   // 4148: masked -> mk = 1 (pure write)
#define TOTAL_BLOCKS (2*COPY_BLOCKS + 2*ONES_BLOCKS)   // 13824

// window-ordered compact lists of global window ids (b*1728+i)
__device__ int g_kept_list[B_ * LEN_KEEP];
__device__ int g_masked_list[B_ * LEN_MASK];

// ---------------------------------------------------------------------------
// Kernel 1 (prep): O(n) selection + compaction, one block per batch.
// Fires the PDL launch-completion trigger at ENTRY so the phase kernel's
// launch/rollout overlaps prep execution; phase blocks hold at
// cudaGridDependencySynchronize() until prep completes.
// ---------------------------------------------------------------------------
__global__ void __launch_bounds__(1024)
prep_kernel(const float* __restrict__ noise) {
    // allow the dependent grid to start launching NOW
    if (threadIdx.x == 0) cudaTriggerProgrammaticLaunchCompletion();

    __shared__ unsigned int sbits[NUM_WIN];
    __shared__ int hist[2048];
    __shared__ int wsum[32];
    __shared__ int s_bucket, s_below;
    __shared__ unsigned long long cand[128];
    __shared__ int cand_cnt;
    __shared__ unsigned long long s_thresh;

    const int b   = blockIdx.x;
    const int tid = threadIdx.x;
    const int lane = tid & 31;
    const int wid  = tid >> 5;

    for (int t = tid; t < NUM_WIN; t += 1024)
        sbits[t] = __float_as_uint(noise[b * NUM_WIN + t]);
    hist[tid] = 0; hist[tid + 1024] = 0;
    if (tid == 0) cand_cnt = 0;
    __syncthreads();

    for (int t = tid; t < NUM_WIN; t += 1024) {
        float v = __uint_as_float(sbits[t]);
        int bk = (int)(v * 2048.0f);
        bk = bk < 0 ? 0 : (bk > 2047 ? 2047 : bk);
        atomicAdd(&hist[bk], 1);
    }
    __syncthreads();

    // ---- scan of 2048 bucket counts (2 buckets per thread) ----
    const int a0 = hist[2 * tid], a1 = hist[2 * tid + 1];
    const int ts = a0 + a1;
    int v = ts;
#pragma unroll
    for (int o = 1; o < 32; o <<= 1) {
        int u = __shfl_up_sync(0xFFFFFFFFu, v, o);
        if (lane >= o) v += u;
    }
    if (lane == 31) wsum[wid] = v;
    __syncthreads();
    if (wid == 0) {
        int w = wsum[lane];
#pragma unroll
        for (int o = 1; o < 32; o <<= 1) {
            int u = __shfl_up_sync(0xFFFFFFFFu, w, o);
            if (lane >= o) w += u;
        }
        wsum[lane] = w;
    }
    __syncthreads();
    const int incl = v + (wid > 0 ? wsum[wid - 1] : 0);
    const int excl_pair = incl - ts;
    if (KSEL >= excl_pair && KSEL < excl_pair + a0) { s_bucket = 2 * tid;     s_below = excl_pair; }
    const int e1 = excl_pair + a0;
    if (KSEL >= e1 && KSEL < e1 + a1)               { s_bucket = 2 * tid + 1; s_below = e1; }
    __syncthreads();

    // ---- gather candidates in the target bucket, rank them exactly ----
    const int tb = s_bucket;
    for (int t = tid; t < NUM_WIN; t += 1024) {
        float fv = __uint_as_float(sbits[t]);
        int bk = (int)(fv * 2048.0f);
        bk = bk < 0 ? 0 : (bk > 2047 ? 2047 : bk);
        if (bk == tb) {
            int p = atomicAdd(&cand_cnt, 1);
            if (p < 128)
                cand[p] = ((unsigned long long)sbits[t] << 11) | (unsigned)t;
        }
    }
    __syncthreads();
    const int m = cand_cnt < 128 ? cand_cnt : 128;
    const int need = KSEL - s_below;
    if (tid < m) {
        unsigned long long k = cand[tid];
        int c = 0;
        for (int j = 0; j < m; j++) c += (cand[j] < k);
        if (c == need) s_thresh = k;
    }
    __syncthreads();
    const unsigned long long thresh = s_thresh;

    // ---- window-ordered compaction: 864 threads x 2 consecutive windows ----
    int cnt = 0, kept0 = 0, kept1 = 0;
    if (tid < 864) {
        const int j0 = 2 * tid, j1 = 2 * tid + 1;
        unsigned long long k0 = ((unsigned long long)sbits[j0] << 11) | (unsigned)j0;
        unsigned long long k1 = ((unsigned long long)sbits[j1] << 11) | (unsigned)j1;
        kept0 = (k0 <= thresh);
        kept1 = (k1 <= thresh);
        cnt = kept0 + kept1;
    }
    int v2 = cnt;
#pragma unroll
    for (int o = 1; o < 32; o <<= 1) {
        int u = __shfl_up_sync(0xFFFFFFFFu, v2, o);
        if (lane >= o) v2 += u;
    }
    if (lane == 31 && wid < 27) wsum[wid] = v2;
    __syncthreads();
    if (wid == 0) {
        int w = (lane < 27) ? wsum[lane] : 0;
#pragma unroll
        for (int o = 1; o < 32; o <<= 1) {
            int u = __shfl_up_sync(0xFFFFFFFFu, w, o);
            if (lane >= o) w += u;
        }
        if (lane < 27) wsum[lane] = w;
    }
    __syncthreads();
    if (tid < 864) {
        const int incl2 = v2 + (wid > 0 ? wsum[wid - 1] : 0);
        const int excl  = incl2 - cnt;          // kept windows before 2*tid
        const int j0 = 2 * tid, j1 = 2 * tid + 1;
        const int gw = b * NUM_WIN;
        if (kept0) g_kept_list[b * LEN_KEEP + excl]          = gw + j0;
        else       g_masked_list[b * LEN_MASK + (j0 - excl)]   = gw + j0;
        const int kb1 = excl + kept0;
        if (kept1) g_kept_list[b * LEN_KEEP + kb1]           = gw + j1;
        else       g_masked_list[b * LEN_MASK + (j1 - kb1)]    = gw + j1;
    }
}

// ---------------------------------------------------------------------------
// Kernel 2: phase kernel, single-stream blocks. Each block = ONE output
// stream of ONE full window (64 segments x 1 KB = 64 KB).
//   bid ranges: [copy kept->xm][ones masked->mk][zeros masked->xm]
//               [zeros kept->mk]
// 3 of 4 phases are data-free constant stores (725 MB pure write); only the
// copy phase reads x. 512 threads, 8 float4 per thread. Launch overlaps prep
// via PDL; holds at cudaGridDependencySynchronize() before touching lists.
// ---------------------------------------------------------------------------
__global__ void __launch_bounds__(512)
phase_kernel(const float4* __restrict__ x,
             float4* __restrict__ out_xm,
             float4* __restrict__ out_mk) {
    const int bid = blockIdx.x;

    int phase, lk;
    if (bid < COPY_BLOCKS)                          { phase = 0; lk = bid; }
    else if (bid < COPY_BLOCKS + ONES_BLOCKS)       { phase = 1; lk = bid - COPY_BLOCKS; }
    else if (bid < COPY_BLOCKS + 2 * ONES_BLOCKS)   { phase = 2; lk = bid - COPY_BLOCKS - ONES_BLOCKS; }
    else                                            { phase = 3; lk = bid - COPY_BLOCKS - 2 * ONES_BLOCKS; }
    const bool from_masked = (phase == 1) || (phase == 2);

    const int t     = threadIdx.x;
    const int seg   = t >> 3;          // 0..63 window segment
    const int lane8 = t & 7;
    const int dh = seg >> 3;
    const int dw = seg & 7;

    cudaGridDependencySynchronize();   // HW wait: prep's writes visible

    const int wglob = from_masked ? __ldg(&g_masked_list[lk])
                                  : __ldg(&g_kept_list[lk]);

    const int b   = wglob / NUM_WIN;
    const int i   = wglob - b * NUM_WIN;
    const int wd3 = i % NWH;
    const int r   = i / NWH;
    const int ww3 = r % NWH;
    const int wh3 = r / NWH;

    const int h = wh3 * 8 + dh;
    const int w = ww3 * 8 + dw;
    // float4 base of this segment (8 voxels along d, 32 channels = 64 float4)
    const int s0 = (((b * H_ + h) * W_ + w) * D_ + wd3 * 8) * 8 + lane8;

    if (phase == 0) {
        // kept: copy x -> xm
        float4 v[8];
#pragma unroll
        for (int k = 0; k < 8; k++)
            v[k] = __ldcs(&x[s0 + k * 8]);
#pragma unroll
        for (int k = 0; k < 8; k++)
            __stcs(&out_xm[s0 + k * 8], v[k]);
    } else {
        const float fv = (phase == 1) ? 1.0f : 0.0f;
        const float4 c = make_float4(fv, fv, fv, fv);
        float4* outp = (phase == 2) ? out_xm : out_mk;
#pragma unroll
        for (int k = 0; k < 8; k++)
            __stcs(&outp[s0 + k * 8], c);
    }
}

extern "C" void kernel_launch(void* const* d_in, const int* in_sizes, int n_in,
                              void* d_out, int out_size) {
    const float* x     = (const float*)d_in[0];   // [B,H,W,D,C] fp32
    const float* noise = (const float*)d_in[1];   // [B, 1728]   fp32
    float* out = (float*)d_out;                   // [x_masked | mask]

    prep_kernel<<<B_, 1024>>>(noise);

    // PDL launch: prep triggers completion at entry, so this grid launches
    // and ramps concurrently with prep; blocks hold at
    // cudaGridDependencySynchronize() until prep's writes are visible.
    cudaLaunchConfig_t cfg = {};
    cfg.gridDim  = dim3(TOTAL_BLOCKS);
    cfg.blockDim = dim3(512);
    cudaLaunchAttribute attrs[1];
    attrs[0].id = cudaLaunchAttributeProgrammaticStreamSerialization;
    attrs[0].val.programmaticStreamSerializationAllowed = 1;
    cfg.attrs = attrs;
    cfg.numAttrs = 1;
    cudaLaunchKernelEx(&cfg, phase_kernel,
                       (const float4*)x,
                       (float4*)out,
                       (float4*)(out + (long long)ELEMS_PER_OUT));
}

// round 10
// speedup vs baseline: 1.0468x; 1.0078x over previous
#include <cuda_runtime.h>
#include <cstdint>

// Shapes (fixed by the problem instance)
#define B_  4
#define H_  96
#define W_  96
#define D_  96
#define NWH 12            // 96/8
#define NUM_WIN 1728      // 12*12*12
#define LEN_KEEP 691      // int(1728*0.4)
#define ELEMS_PER_OUT (B_*H_*W_*D_*32)   // 113,246,208 floats

#define NWTOT (B_ * NUM_WIN)             // 6912 windows total
#define TOTAL_BLOCKS (2 * NWTOT)         // 13824: xm stream + mk stream

// ---------------------------------------------------------------------------
// Single fused kernel, no inter-block synchronization.
// Block bid < NWTOT : writes the x_masked stream of window bid
//                     (kept -> copy x, masked -> zeros).
// Block bid >= NWTOT: writes the mask stream of window bid-NWTOT
//                     (kept -> 0.0, masked -> 1.0; constant either way).
// Each block decides kept/masked by computing its own window's rank among
// the batch's 1728 noise keys (stable-argsort equivalent):
//   rank_i = #{ j : noise_j < noise_i  or (noise_j == noise_i and j < i) }
//   kept   = rank_i < LEN_KEEP
// 1728 values / 512 threads = ~3.4 compares per thread + one block reduce;
// noise is L2-resident after the first wave, so the prologue is ~300-500ns
// and fully overlapped with co-resident blocks' memory traffic.
// Each block writes exactly ONE output stream of ONE window: 64 segments of
// 1 KB (8 voxels along d x 32 channels), 8 float4 per thread.
// ---------------------------------------------------------------------------
__global__ void __launch_bounds__(512)
fused_kernel(const float4* __restrict__ x,
             float4* __restrict__ out_xm,
             float4* __restrict__ out_mk,
             const float* __restrict__ noise) {
    __shared__ int wred[16];
    __shared__ int s_rank;

    const int bid   = blockIdx.x;
    const bool is_xm = (bid < NWTOT);
    const int g = is_xm ? bid : bid - NWTOT;   // global window id
    const int b = g / NUM_WIN;
    const int i = g - b * NUM_WIN;             // window index within batch

    const int tid  = threadIdx.x;
    const int lane = tid & 31;
    const int wid  = tid >> 5;

    // ---- rank of window i within batch b (all threads cooperate) ----
    const float* nb = noise + b * NUM_WIN;
    const unsigned int vbits = __float_as_uint(__ldg(&nb[i]));  // broadcast
    int cnt = 0;
#pragma unroll
    for (int k = 0; k < 4; k++) {
        const int j = tid + k * 512;
        if (j < NUM_WIN) {
            const unsigned int u = __float_as_uint(__ldg(&nb[j]));
            // float compare on raw bits is fine: noise in [0,1) (positive)
            cnt += (u < vbits) || (u == vbits && j < i);
        }
    }
#pragma unroll
    for (int o = 16; o > 0; o >>= 1)
        cnt += __shfl_xor_sync(0xFFFFFFFFu, cnt, o);
    if (lane == 0) wred[wid] = cnt;
    __syncthreads();
    if (tid == 0) {
        int r = 0;
#pragma unroll
        for (int k = 0; k < 16; k++) r += wred[k];
        s_rank = r;
    }
    __syncthreads();
    const bool kept = (s_rank < LEN_KEEP);

    // ---- geometry: this block's window -> 64 KB output region ----
    const int wd3 = i % NWH;
    const int r2  = i / NWH;
    const int ww3 = r2 % NWH;
    const int wh3 = r2 / NWH;

    const int seg   = tid >> 3;        // 0..63 window segment
    const int lane8 = tid & 7;
    const int dh = seg >> 3;
    const int dw = seg & 7;
    const int h = wh3 * 8 + dh;
    const int w = ww3 * 8 + dw;
    // float4 base of this segment (8 voxels along d, 32 channels = 64 float4)
    const int s0 = (((b * H_ + h) * W_ + w) * D_ + wd3 * 8) * 8 + lane8;

    if (is_xm) {
        if (kept) {
            float4 v[8];
#pragma unroll
            for (int k = 0; k < 8; k++)
                v[k] = __ldcs(&x[s0 + k * 8]);
#pragma unroll
            for (int k = 0; k < 8; k++)
                __stcs(&out_xm[s0 + k * 8], v[k]);
        } else {
            const float4 z = make_float4(0.f, 0.f, 0.f, 0.f);
#pragma unroll
            for (int k = 0; k < 8; k++)
                __stcs(&out_xm[s0 + k * 8], z);
        }
    } else {
        const float fv = kept ? 0.0f : 1.0f;
        const float4 c = make_float4(fv, fv, fv, fv);
#pragma unroll
        for (int k = 0; k < 8; k++)
            __stcs(&out_mk[s0 + k * 8], c);
    }
}

extern "C" void kernel_launch(void* const* d_in, const int* in_sizes, int n_in,
                              void* d_out, int out_size) {
    const float* x     = (const float*)d_in[0];   // [B,H,W,D,C] fp32
    const float* noise = (const float*)d_in[1];   // [B, 1728]   fp32
    float* out = (float*)d_out;                   // [x_masked | mask]

    fused_kernel<<<TOTAL_BLOCKS, 512>>>(
        (const float4*)x,
        (float4*)out,
        (float4*)(out + (long long)ELEMS_PER_OUT),
        noise);
}